// round 14
// baseline (speedup 1.0000x reference)
#include <cuda_runtime.h>
#include <cuda_bf16.h>

// ---------------------------------------------------------------------------
// PatchTokenizer: entropy-masked multi-scale patch gather.
// Output layout (float32, tuple order, concatenated):
//   sel16 | full32 | sel32 | flat16 | flat32 | output_mask | seqlens |
//   cu_seqlens | max_seqlen | retained_frac
// ---------------------------------------------------------------------------

#define NCOARSE 8192    // 32 * 16 * 16
#define NFINE   32768   // 32 * 32 * 32

typedef unsigned long long u64;

__device__ int d_m32[NCOARSE];        // coarse keep mask (entropy < 7.2)
__device__ int d_idx32[NCOARSE + 1];  // exclusive prefix of m32 (+ sentinel N32)
__device__ int d_off[6];              // {full32_f4, sel32_f4, OFF_f16, OFF_f32, OFF_mask, sumseq}
__device__ int d_cu[33];              // per-batch cu_seqlens (int)
__device__ int d_n32b[32];            // per-batch coarse kept count

__device__ __forceinline__ u64 l2_evict_last_policy()
{
    u64 pol;
    asm("createpolicy.fractional.L2::evict_last.b64 %0, 1.0;" : "=l"(pol));
    return pol;
}

__device__ __forceinline__ float4 ldg_evict_last(const float4* p, u64 pol)
{
    float4 v;
    asm volatile("ld.global.L2::cache_hint.v4.f32 {%0,%1,%2,%3}, [%4], %5;"
                 : "=f"(v.x), "=f"(v.y), "=f"(v.z), "=f"(v.w)
                 : "l"(p), "l"(pol));
    return v;
}

// 256-bit global ops (sm_100a: ld/st.global.v8.f32)
__device__ __forceinline__ void ldg256(const float4* p, float4& a, float4& b)
{
    asm volatile("ld.global.v8.f32 {%0,%1,%2,%3,%4,%5,%6,%7}, [%8];"
                 : "=f"(a.x), "=f"(a.y), "=f"(a.z), "=f"(a.w),
                   "=f"(b.x), "=f"(b.y), "=f"(b.z), "=f"(b.w)
                 : "l"(p));
}

__device__ __forceinline__ void stg256_cs(float4* p, const float4& a, const float4& b)
{
    asm volatile("st.global.cs.v8.f32 [%0], {%1,%2,%3,%4,%5,%6,%7,%8};"
                 :: "l"(p),
                    "f"(a.x), "f"(a.y), "f"(a.z), "f"(a.w),
                    "f"(b.x), "f"(b.y), "f"(b.z), "f"(b.w)
                 : "memory");
}

// ---------------- Kernel 1: per-coarse-patch histogram entropy -------------
// (unchanged from 57.3us baseline)
__global__ void __launch_bounds__(256) entropy_kernel(
    const float* __restrict__ img, const float* __restrict__ mean,
    const float* __restrict__ stdv)
{
    __shared__ int hist[512];
    const int p = blockIdx.x;          // coarse patch id
    const int t = threadIdx.x;         // 256 threads
    hist[t] = 0; hist[t + 256] = 0;
    __syncthreads();

    const int b  = p >> 8;
    const int ic = (p >> 4) & 15;
    const int jc = p & 15;
    const float s0 = stdv[0] * 255.0f, s1 = stdv[1] * 255.0f, s2 = stdv[2] * 255.0f;
    const float m0 = mean[0] * 255.0f, m1 = mean[1] * 255.0f, m2 = mean[2] * 255.0f;
    const float4* base4 = (const float4*)(img + (size_t)b * 786432);

    const u64 pol = l2_evict_last_policy();
    const int r  = t >> 3;
    const int f4 = t & 7;
    const int a  = (ic * 32 + r) * 128 + jc * 8 + f4;
    float4 v0 = ldg_evict_last(base4 + a, pol);
    float4 v1 = ldg_evict_last(base4 + 65536 + a, pol);
    float4 v2 = ldg_evict_last(base4 + 131072 + a, pol);

    #pragma unroll
    for (int i = 0; i < 4; i++) {
        float u0 = fminf(fmaxf(fmaf((&v0.x)[i], s0, m0), 0.0f), 255.0f);
        float u1 = fminf(fmaxf(fmaf((&v1.x)[i], s1, m1), 0.0f), 255.0f);
        float u2 = fminf(fmaxf(fmaf((&v2.x)[i], s2, m2), 0.0f), 255.0f);
        float gray = fmaf(u0, 0.2989f, fmaf(u1, 0.587f, u2 * 0.114f));
        int bin = (int)(gray * 2.0f);      // gray in [0, 254.98] -> bin in [0, 509]
        atomicAdd(&hist[bin], 1);
    }
    __syncthreads();

    float e = 0.0f;
    #pragma unroll
    for (int i = 0; i < 2; i++) {
        int c = hist[t + i * 256];
        if (c) {
            float pr = (float)c * (1.0f / 1024.0f);
            e -= pr * __log2f(pr + 1e-10f);   // single MUFU.LG2
        }
    }
    #pragma unroll
    for (int d = 16; d > 0; d >>= 1) e += __shfl_down_sync(0xffffffffu, e, d);
    __shared__ float we[8];
    int lane = t & 31, wid = t >> 5;
    if (lane == 0) we[wid] = e;
    __syncthreads();
    if (t == 0) {
        float s = 0.0f;
        #pragma unroll
        for (int i = 0; i < 8; i++) s += we[i];
        d_m32[p] = (s < 7.2f) ? 1 : 0;
    }
}

// ---------------- block-wide exclusive scan (blockDim = 1024) --------------
__device__ __forceinline__ int block_excl_scan(int v, int& tot)
{
    __shared__ int ws[32];
    __shared__ int stot;
    const int lane = threadIdx.x & 31, wid = threadIdx.x >> 5;
    int x = v;
    #pragma unroll
    for (int d = 1; d < 32; d <<= 1) {
        int y = __shfl_up_sync(0xffffffffu, x, d);
        if (lane >= d) x += y;
    }
    if (lane == 31) ws[wid] = x;
    __syncthreads();
    if (wid == 0) {
        int w = ws[lane];
        int xx = w;
        #pragma unroll
        for (int d = 1; d < 32; d <<= 1) {
            int y = __shfl_up_sync(0xffffffffu, xx, d);
            if (lane >= d) xx += y;
        }
        ws[lane] = xx - w;              // exclusive warp-prefix
        if (lane == 31) stot = xx;
    }
    __syncthreads();
    tot = stot;
    int rr = ws[wid] + x - v;
    __syncthreads();
    return rr;
}

// ---------------- Kernel 2: coarse prefix sum + scalar outputs -------------
__global__ void __launch_bounds__(1024) scan_kernel(float* __restrict__ out)
{
    const int t = threadIdx.x;          // 1024 threads, 1 block
    __shared__ int sh_n32[32];
    __shared__ int sh_cu[33];

    // coarse scan: 8 elems/thread
    int cv[8]; int csum = 0;
    #pragma unroll
    for (int i = 0; i < 8; i++) { cv[i] = d_m32[t * 8 + i]; csum += cv[i]; }
    int tot32;
    int cex = block_excl_scan(csum, tot32);
    {
        int e = cex;
        #pragma unroll
        for (int i = 0; i < 8; i++) { d_idx32[t * 8 + i] = e; e += cv[i]; }
    }
    __syncthreads();

    const int N32 = tot32;
    const int N16 = NFINE - 4 * N32;

    if (t < 32) {
        int start = d_idx32[t * 256];
        int end   = (t == 31) ? N32 : d_idx32[(t + 1) * 256];
        sh_n32[t] = end - start;
    }
    __syncthreads();
    if (t == 0) {
        int acc = 0; sh_cu[0] = 0;
        for (int b = 0; b < 32; b++) { acc += 1025 - 3 * sh_n32[b]; sh_cu[b + 1] = acc; }
    }
    __syncthreads();

    const int sumseq   = sh_cu[32];           // = 32 + N16 + N32
    const int OFF1     = N16 * 768;
    const int OFF2     = OFF1 + N32 * 3072;
    const int OFF_f16  = OFF2 + N32 * 768;
    const int OFF_f32  = OFF_f16 + NFINE;
    const int OFF_mask = OFF_f32 + NCOARSE;
    const int OFF_seq  = OFF_mask + sumseq;
    const int OFF_cu   = OFF_seq + 32;
    const int OFF_max  = OFF_cu + 33;
    const int OFF_frac = OFF_max + 1;

    if (t < 32) {
        d_n32b[t] = sh_n32[t];
        d_cu[t]   = sh_cu[t];
        out[OFF_seq + t] = (float)(1025 - 3 * sh_n32[t]);
        out[OFF_cu + t]  = (float)sh_cu[t];
    }
    if (t == 0) {
        d_idx32[NCOARSE] = N32;               // sentinel for row-end lookups
        d_cu[32] = sh_cu[32];
        d_off[0] = N16 * 192;                 // full32 start, float4 units
        d_off[1] = N16 * 192 + N32 * 768;     // sel32 start, float4 units
        d_off[2] = OFF_f16;
        d_off[3] = OFF_f32;
        d_off[4] = OFF_mask;
        d_off[5] = sumseq;
        out[OFF_cu + 32] = (float)sh_cu[32];
        int mx = 0;
        for (int b = 0; b < 32; b++) mx = max(mx, 1025 - 3 * sh_n32[b]);
        out[OFF_max]  = (float)mx;
        out[OFF_frac] = (float)sumseq / 32768.0f;
    }
}

// ---------------- Kernel 3: 256-bit gathers (reverse order) + fills --------
// 384 threads/block, 8 coarse patches/block, grid 1024, reverse p order.
// Each thread owns one 32B slot per patch: c=t>>7, k=(t&127)>>5,
// row rr=(t&31)>>1, half h2=t&1. One ld.v8 + one st.cs.v8 per patch,
// batched 4 patches deep for MLP.
__global__ void __launch_bounds__(384) gather_kernel(
    const float* __restrict__ img, float* __restrict__ out)
{
    const int B  = blockIdx.x;         // 1024 blocks
    const int t  = threadIdx.x;        // 384 threads
    const int p0 = (1023 - B) * 8;     // reverse order; 8 patches, same row
    const int b  = p0 >> 8;            // 32 blocks per batch
    const float4* base4 = (const float4*)(img + (size_t)b * 786432);
    float4* out4 = (float4*)out;

    const int c  = t >> 7;             // channel 0..2
    const int u  = t & 127;            // 32B slot within channel
    const int k  = u >> 5;             // sub-patch 0..3
    const int rw = u & 31;
    const int rr = rw >> 1, h2 = rw & 1;
    const int di = k >> 1, dj = k & 1;

    const int off0 = d_off[0];
    const int off1 = d_off[1];

    // stage masks + coarse prefixes; derive fine slots analytically
    __shared__ int sm[8], sslot[8], srow[2];   // srow = {idx32[prs], idx32[prs+16]}
    if (t < 8) { sm[t] = d_m32[p0 + t]; sslot[t] = d_idx32[p0 + t]; }
    if (t == 16) srow[0] = d_idx32[p0 & ~15];
    if (t == 17) srow[1] = d_idx32[(p0 & ~15) + 16];
    __syncthreads();

    const int prs    = p0 & ~15;
    const int Urs    = prs - srow[0];               // unkept coarse before row
    const int Urowt  = (prs + 16 - srow[1]) - Urs;  // unkept in whole row

    // per-thread fixed offsets
    const int yloc  = di * 16 + rr;                 // row within patch quadrant
    const int xloc  = dj * 4 + h2 * 2;              // f4 offset within patch
    const int dloc  = c * 64 + rr * 4 + h2 * 2;     // f4 offset within 16x16 slot

    #pragma unroll
    for (int g = 0; g < 2; g++) {
        float4 va[4], vb[4];
        #pragma unroll
        for (int q = 0; q < 4; q++) {
            const int p  = p0 + g * 4 + q;
            const int ic = (p >> 4) & 15;
            const int jc = p & 15;
            ldg256(base4 + c * 65536 + (ic * 32 + yloc) * 128 + jc * 8 + xloc,
                   va[q], vb[q]);
        }
        #pragma unroll
        for (int q = 0; q < 4; q++) {
            const int kp = g * 4 + q;
            const int p  = p0 + kp;
            if (!sm[kp]) {
                const int Urow = (p - sslot[kp]) - Urs; // unkept before p in row
                const int dstk = 4 * Urs + 2 * Urow + 2 * di * Urowt + dj;
                stg256_cs(&out4[(size_t)dstk * 192 + dloc], va[q], vb[q]);
            } else {
                stg256_cs(&out4[(size_t)off0 + (size_t)sslot[kp] * 768 +
                                k * 192 + dloc], va[q], vb[q]);
            }
        }
    }

    // sel32 for kept patches (rare path): old 192-thread mapping
    if (t < 192) {
        const int c2 = t >> 6;
        const int w0 = t & 63;
        const int r2 = w0 >> 2, s42 = w0 & 3;
        #pragma unroll
        for (int kp = 0; kp < 8; kp++) {
            if (sm[kp]) {
                const int p  = p0 + kp;
                const int ic = (p >> 4) & 15;
                const int jc = p & 15;
                int y0 = ic * 32 + 2 * r2;
                int xb = jc * 8 + 2 * s42;
                float4 a0 = base4[c2 * 65536 + y0 * 128 + xb];
                float4 a1 = base4[c2 * 65536 + y0 * 128 + xb + 1];
                float4 b0 = base4[c2 * 65536 + (y0 + 1) * 128 + xb];
                float4 b1 = base4[c2 * 65536 + (y0 + 1) * 128 + xb + 1];
                float4 o;
                o.x = 0.25f * (a0.x + a0.y + b0.x + b0.y);
                o.y = 0.25f * (a0.z + a0.w + b0.z + b0.w);
                o.z = 0.25f * (a1.x + a1.y + b1.x + b1.y);
                o.w = 0.25f * (a1.z + a1.w + b1.z + b1.w);
                __stcs(&out4[(size_t)off1 + (size_t)sslot[kp] * 192 + t], o);
            }
        }
    }

    // ---- dense fills: flat16 | flat32 | output_mask -----------------------
    {
        const int gi = B * 384 + t;
        const int T  = 40960 + d_off[5];       // 32768 + 8192 + sumseq
        if (gi < T) {
            if (gi < 32768) {
                int q = gi;
                int m = d_m32[(q >> 10) * 256 + (((q >> 5) & 31) >> 1) * 16 + ((q & 31) >> 1)];
                out[d_off[2] + q] = (float)(1 - m);
            } else if (gi < 40960) {
                int p = gi - 32768;
                out[d_off[3] + p] = (float)d_m32[p];
            } else {
                int j = gi - 40960;            // index into output_mask
                int lo = 0, hi = 32;
                while (hi - lo > 1) {
                    int mid = (lo + hi) >> 1;
                    if (j >= d_cu[mid]) lo = mid; else hi = mid;
                }
                int rel  = j - d_cu[lo];
                int n16b = 1024 - 4 * d_n32b[lo];
                float val = (rel == 0) ? -1.0f : (rel - 1 < n16b ? 1.0f : 2.0f);
                out[d_off[4] + j] = val;
            }
        }
    }
}

// ---------------------------------------------------------------------------
extern "C" void kernel_launch(void* const* d_in, const int* in_sizes, int n_in,
                              void* d_out, int out_size)
{
    const float* img  = (const float*)d_in[0];
    const float* mean = (const float*)d_in[1];
    const float* stdv = (const float*)d_in[2];
    float* out = (float*)d_out;

    entropy_kernel<<<NCOARSE, 256>>>(img, mean, stdv);
    scan_kernel<<<1, 1024>>>(out);
    gather_kernel<<<1024, 384>>>(img, out);
}

// round 15
// speedup vs baseline: 1.0575x; 1.0575x over previous
#include <cuda_runtime.h>
#include <cuda_bf16.h>

// ---------------------------------------------------------------------------
// PatchTokenizer: entropy-masked multi-scale patch gather.
// Output layout (float32, tuple order, concatenated):
//   sel16 | full32 | sel32 | flat16 | flat32 | output_mask | seqlens |
//   cu_seqlens | max_seqlen | retained_frac
// ---------------------------------------------------------------------------

#define NCOARSE 8192    // 32 * 16 * 16
#define NFINE   32768   // 32 * 32 * 32

typedef unsigned long long u64;

__device__ int d_m32[NCOARSE];        // coarse keep mask (entropy < 7.2)
__device__ int d_idx32[NCOARSE + 1];  // exclusive prefix of m32 (+ sentinel N32)
__device__ int d_off[6];              // {full32_f4, sel32_f4, OFF_f16, OFF_f32, OFF_mask, sumseq}
__device__ int d_cu[33];              // per-batch cu_seqlens (int)
__device__ int d_n32b[32];            // per-batch coarse kept count

__device__ __forceinline__ u64 l2_evict_last_policy()
{
    u64 pol;
    asm("createpolicy.fractional.L2::evict_last.b64 %0, 1.0;" : "=l"(pol));
    return pol;
}

__device__ __forceinline__ float4 ldg_evict_last(const float4* p, u64 pol)
{
    float4 v;
    asm volatile("ld.global.L2::cache_hint.v4.f32 {%0,%1,%2,%3}, [%4], %5;"
                 : "=f"(v.x), "=f"(v.y), "=f"(v.z), "=f"(v.w)
                 : "l"(p), "l"(pol));
    return v;
}

// ---------------- Kernel 1: per-coarse-patch histogram entropy -------------
__global__ void __launch_bounds__(256) entropy_kernel(
    const float* __restrict__ img, const float* __restrict__ mean,
    const float* __restrict__ stdv)
{
    __shared__ int hist[512];
    const int p = blockIdx.x;          // coarse patch id
    const int t = threadIdx.x;         // 256 threads
    hist[t] = 0; hist[t + 256] = 0;
    __syncthreads();

    const int b  = p >> 8;
    const int ic = (p >> 4) & 15;
    const int jc = p & 15;
    const float s0 = stdv[0] * 255.0f, s1 = stdv[1] * 255.0f, s2 = stdv[2] * 255.0f;
    const float m0 = mean[0] * 255.0f, m1 = mean[1] * 255.0f, m2 = mean[2] * 255.0f;
    const float4* base4 = (const float4*)(img + (size_t)b * 786432);

    const u64 pol = l2_evict_last_policy();
    const int r  = t >> 3;
    const int f4 = t & 7;
    const int a  = (ic * 32 + r) * 128 + jc * 8 + f4;
    float4 v0 = ldg_evict_last(base4 + a, pol);
    float4 v1 = ldg_evict_last(base4 + 65536 + a, pol);
    float4 v2 = ldg_evict_last(base4 + 131072 + a, pol);

    #pragma unroll
    for (int i = 0; i < 4; i++) {
        float u0 = fminf(fmaxf(fmaf((&v0.x)[i], s0, m0), 0.0f), 255.0f);
        float u1 = fminf(fmaxf(fmaf((&v1.x)[i], s1, m1), 0.0f), 255.0f);
        float u2 = fminf(fmaxf(fmaf((&v2.x)[i], s2, m2), 0.0f), 255.0f);
        float gray = fmaf(u0, 0.2989f, fmaf(u1, 0.587f, u2 * 0.114f));
        int bin = (int)(gray * 2.0f);      // gray in [0, 254.98] -> bin in [0, 509]
        atomicAdd(&hist[bin], 1);
    }
    __syncthreads();

    float e = 0.0f;
    #pragma unroll
    for (int i = 0; i < 2; i++) {
        int c = hist[t + i * 256];
        if (c) {
            float pr = (float)c * (1.0f / 1024.0f);
            e -= pr * __log2f(pr + 1e-10f);   // single MUFU.LG2
        }
    }
    #pragma unroll
    for (int d = 16; d > 0; d >>= 1) e += __shfl_down_sync(0xffffffffu, e, d);
    __shared__ float we[8];
    int lane = t & 31, wid = t >> 5;
    if (lane == 0) we[wid] = e;
    __syncthreads();
    if (t == 0) {
        float s = 0.0f;
        #pragma unroll
        for (int i = 0; i < 8; i++) s += we[i];
        d_m32[p] = (s < 7.2f) ? 1 : 0;
    }
}

// ---------------- block-wide exclusive scan (blockDim = 1024) --------------
__device__ __forceinline__ int block_excl_scan(int v, int& tot)
{
    __shared__ int ws[32];
    __shared__ int stot;
    const int lane = threadIdx.x & 31, wid = threadIdx.x >> 5;
    int x = v;
    #pragma unroll
    for (int d = 1; d < 32; d <<= 1) {
        int y = __shfl_up_sync(0xffffffffu, x, d);
        if (lane >= d) x += y;
    }
    if (lane == 31) ws[wid] = x;
    __syncthreads();
    if (wid == 0) {
        int w = ws[lane];
        int xx = w;
        #pragma unroll
        for (int d = 1; d < 32; d <<= 1) {
            int y = __shfl_up_sync(0xffffffffu, xx, d);
            if (lane >= d) xx += y;
        }
        ws[lane] = xx - w;              // exclusive warp-prefix
        if (lane == 31) stot = xx;
    }
    __syncthreads();
    tot = stot;
    int rr = ws[wid] + x - v;
    __syncthreads();
    return rr;
}

// ---------------- Kernel 2: coarse prefix sum + scalar outputs -------------
// PDL secondary: wait for entropy grid before reading d_m32.
__global__ void __launch_bounds__(1024) scan_kernel(float* __restrict__ out)
{
    const int t = threadIdx.x;          // 1024 threads, 1 block
    __shared__ int sh_n32[32];
    __shared__ int sh_cu[33];

    cudaGridDependencySynchronize();    // entropy's d_m32 writes visible after

    // coarse scan: 8 elems/thread
    int cv[8]; int csum = 0;
    #pragma unroll
    for (int i = 0; i < 8; i++) { cv[i] = d_m32[t * 8 + i]; csum += cv[i]; }
    int tot32;
    int cex = block_excl_scan(csum, tot32);
    {
        int e = cex;
        #pragma unroll
        for (int i = 0; i < 8; i++) { d_idx32[t * 8 + i] = e; e += cv[i]; }
    }
    __syncthreads();

    const int N32 = tot32;
    const int N16 = NFINE - 4 * N32;

    if (t < 32) {
        int start = d_idx32[t * 256];
        int end   = (t == 31) ? N32 : d_idx32[(t + 1) * 256];
        sh_n32[t] = end - start;
    }
    __syncthreads();
    if (t == 0) {
        int acc = 0; sh_cu[0] = 0;
        for (int b = 0; b < 32; b++) { acc += 1025 - 3 * sh_n32[b]; sh_cu[b + 1] = acc; }
    }
    __syncthreads();

    const int sumseq   = sh_cu[32];           // = 32 + N16 + N32
    const int OFF1     = N16 * 768;
    const int OFF2     = OFF1 + N32 * 3072;
    const int OFF_f16  = OFF2 + N32 * 768;
    const int OFF_f32  = OFF_f16 + NFINE;
    const int OFF_mask = OFF_f32 + NCOARSE;
    const int OFF_seq  = OFF_mask + sumseq;
    const int OFF_cu   = OFF_seq + 32;
    const int OFF_max  = OFF_cu + 33;
    const int OFF_frac = OFF_max + 1;

    if (t < 32) {
        d_n32b[t] = sh_n32[t];
        d_cu[t]   = sh_cu[t];
        out[OFF_seq + t] = (float)(1025 - 3 * sh_n32[t]);
        out[OFF_cu + t]  = (float)sh_cu[t];
    }
    if (t == 0) {
        d_idx32[NCOARSE] = N32;               // sentinel for row-end lookups
        d_cu[32] = sh_cu[32];
        d_off[0] = N16 * 192;                 // full32 start, float4 units
        d_off[1] = N16 * 192 + N32 * 768;     // sel32 start, float4 units
        d_off[2] = OFF_f16;
        d_off[3] = OFF_f32;
        d_off[4] = OFF_mask;
        d_off[5] = sumseq;
        out[OFF_cu + 32] = (float)sh_cu[32];
        int mx = 0;
        for (int b = 0; b < 32; b++) mx = max(mx, 1025 - 3 * sh_n32[b]);
        out[OFF_max]  = (float)mx;
        out[OFF_frac] = (float)sumseq / 32768.0f;
    }
}

// ---------------- Kernel 3: gathers (reverse order) + dense fills ----------
// PDL secondary: prologue (index math) runs during scan's tail; waits before
// reading scan outputs. 384 threads, 8 patches/block, grid 1024, reverse p.
__global__ void __launch_bounds__(384) gather_kernel(
    const float* __restrict__ img, float* __restrict__ out)
{
    const int B  = blockIdx.x;         // 1024 blocks
    const int t  = threadIdx.x;        // 384 threads
    const int p0 = (1023 - B) * 8;     // reverse order; 8 patches, same row
    const int b  = p0 >> 8;            // 32 blocks per batch
    const float4* base4 = (const float4*)(img + (size_t)b * 786432);
    float4* out4 = (float4*)out;

    const int h  = t >= 192;           // half: patches 4h..4h+3
    const int tl = t - h * 192;        // local thread 0..191
    const int c  = tl >> 6;            // channel 0..2
    const int w0 = tl & 63;
    const int r  = w0 >> 2, s4 = w0 & 3;

    cudaGridDependencySynchronize();   // scan's d_idx32/d_off/d_cu visible after

    const int off0 = d_off[0];
    const int off1 = d_off[1];

    // stage masks + coarse prefixes; derive fine slots analytically
    __shared__ int sm[8], sslot[8], srow[2];   // srow = {idx32[prs], idx32[prs+16]}
    if (t < 8) { sm[t] = d_m32[p0 + t]; sslot[t] = d_idx32[p0 + t]; }
    if (t == 16) srow[0] = d_idx32[p0 & ~15];
    if (t == 17) srow[1] = d_idx32[(p0 & ~15) + 16];
    __syncthreads();

    const int prs    = p0 & ~15;
    const int Urs    = prs - srow[0];               // unkept coarse before row
    const int Urowt  = (prs + 16 - srow[1]) - Urs;  // unkept in whole row

    #pragma unroll
    for (int kq = 0; kq < 4; kq++) {
        const int kp = h * 4 + kq;
        const int p  = p0 + kp;
        const int ic = (p >> 4) & 15;
        const int jc = p & 15;
        float4 v[4];
        #pragma unroll
        for (int k = 0; k < 4; k++) {
            int di = k >> 1, dj = k & 1;
            int y  = ic * 32 + di * 16 + r;
            int xs = jc * 8 + dj * 4 + s4;
            v[k] = base4[c * 65536 + y * 128 + xs];
        }
        if (!sm[kp]) {
            const int u    = 1;                     // this patch unkept
            const int Urow = (p - sslot[kp]) - Urs; // unkept before p in row
            int dst16[4];
            dst16[0] = 4 * Urs + 2 * Urow;              // (di=0,dj=0)
            dst16[1] = dst16[0] + u;                    // (0,1)
            dst16[2] = 4 * Urs + 2 * Urowt + 2 * Urow;  // (1,0)
            dst16[3] = dst16[2] + u;                    // (1,1)
            #pragma unroll
            for (int k = 0; k < 4; k++)
                __stcs(&out4[(size_t)dst16[k] * 192 + c * 64 + w0], v[k]);
        } else {
            const size_t o1 = (size_t)off0 + (size_t)sslot[kp] * 768;
            #pragma unroll
            for (int k = 0; k < 4; k++)
                __stcs(&out4[o1 + k * 192 + c * 64 + w0], v[k]);
            // sel32: 2x2-mean downsample (source lines L1-hot from v[] loads)
            {
                int y0 = ic * 32 + 2 * r;
                int xb = jc * 8 + 2 * s4;
                float4 a0 = base4[c * 65536 + y0 * 128 + xb];
                float4 a1 = base4[c * 65536 + y0 * 128 + xb + 1];
                float4 b0 = base4[c * 65536 + (y0 + 1) * 128 + xb];
                float4 b1 = base4[c * 65536 + (y0 + 1) * 128 + xb + 1];
                float4 o;
                o.x = 0.25f * (a0.x + a0.y + b0.x + b0.y);
                o.y = 0.25f * (a0.z + a0.w + b0.z + b0.w);
                o.z = 0.25f * (a1.x + a1.y + b1.x + b1.y);
                o.w = 0.25f * (a1.z + a1.w + b1.z + b1.w);
                __stcs(&out4[(size_t)off1 + (size_t)sslot[kp] * 192 + tl], o);
            }
        }
    }

    // ---- dense fills: flat16 | flat32 | output_mask -----------------------
    {
        const int gi = B * 384 + t;
        const int T  = 40960 + d_off[5];       // 32768 + 8192 + sumseq
        if (gi < T) {
            if (gi < 32768) {
                int q = gi;
                int m = d_m32[(q >> 10) * 256 + (((q >> 5) & 31) >> 1) * 16 + ((q & 31) >> 1)];
                out[d_off[2] + q] = (float)(1 - m);
            } else if (gi < 40960) {
                int p = gi - 32768;
                out[d_off[3] + p] = (float)d_m32[p];
            } else {
                int j = gi - 40960;            // index into output_mask
                int lo = 0, hi = 32;
                while (hi - lo > 1) {
                    int mid = (lo + hi) >> 1;
                    if (j >= d_cu[mid]) lo = mid; else hi = mid;
                }
                int rel  = j - d_cu[lo];
                int n16b = 1024 - 4 * d_n32b[lo];
                float val = (rel == 0) ? -1.0f : (rel - 1 < n16b ? 1.0f : 2.0f);
                out[d_off[4] + j] = val;
            }
        }
    }
}

// ---------------------------------------------------------------------------
extern "C" void kernel_launch(void* const* d_in, const int* in_sizes, int n_in,
                              void* d_out, int out_size)
{
    const float* img  = (const float*)d_in[0];
    const float* mean = (const float*)d_in[1];
    const float* stdv = (const float*)d_in[2];
    float* out = (float*)d_out;

    entropy_kernel<<<NCOARSE, 256>>>(img, mean, stdv);

    // PDL launches: dependent kernels overlap their prologue with the
    // predecessor's tail; cudaGridDependencySynchronize() guards data reads.
    cudaLaunchAttribute attrs[1];
    attrs[0].id = cudaLaunchAttributeProgrammaticStreamSerialization;
    attrs[0].val.programmaticStreamSerializationAllowed = 1;

    {
        cudaLaunchConfig_t cfg = {};
        cfg.gridDim  = dim3(1, 1, 1);
        cfg.blockDim = dim3(1024, 1, 1);
        cfg.attrs    = attrs;
        cfg.numAttrs = 1;
        cudaLaunchKernelEx(&cfg, scan_kernel, out);
    }
    {
        cudaLaunchConfig_t cfg = {};
        cfg.gridDim  = dim3(1024, 1, 1);
        cfg.blockDim = dim3(384, 1, 1);
        cfg.attrs    = attrs;
        cfg.numAttrs = 1;
        cudaLaunchKernelEx(&cfg, gather_kernel, img, out);
    }
}

// round 16
// speedup vs baseline: 1.0741x; 1.0156x over previous
#include <cuda_runtime.h>
#include <cuda_bf16.h>

// ---------------------------------------------------------------------------
// PatchTokenizer: entropy-masked multi-scale patch gather.
// Output layout (float32, tuple order, concatenated):
//   sel16 | full32 | sel32 | flat16 | flat32 | output_mask | seqlens |
//   cu_seqlens | max_seqlen | retained_frac
// ---------------------------------------------------------------------------

#define NCOARSE 8192    // 32 * 16 * 16
#define NFINE   32768   // 32 * 32 * 32

typedef unsigned long long u64;

__device__ int d_m32[NCOARSE];        // coarse keep mask (entropy < 7.2)
__device__ int d_idx32[NCOARSE + 1];  // exclusive prefix of m32 (+ sentinel N32)
__device__ int d_off[6];              // {full32_f4, sel32_f4, OFF_f16, OFF_f32, OFF_mask, sumseq}
__device__ int d_cu[33];              // per-batch cu_seqlens (int)
__device__ int d_n32b[32];            // per-batch coarse kept count

__device__ __forceinline__ u64 l2_evict_last_policy()
{
    u64 pol;
    asm("createpolicy.fractional.L2::evict_last.b64 %0, 1.0;" : "=l"(pol));
    return pol;
}

__device__ __forceinline__ float4 ldg_evict_last(const float4* p, u64 pol)
{
    float4 v;
    asm volatile("ld.global.L2::cache_hint.v4.f32 {%0,%1,%2,%3}, [%4], %5;"
                 : "=f"(v.x), "=f"(v.y), "=f"(v.z), "=f"(v.w)
                 : "l"(p), "l"(pol));
    return v;
}

// ---------------- Kernel 1: per-coarse-patch histogram entropy -------------
// 256 threads, 2 patches per block, 6 independent loads per thread (MLP=6),
// two independent 512-bin shared histograms. Grid 4096.
__global__ void __launch_bounds__(256) entropy_kernel(
    const float* __restrict__ img, const float* __restrict__ mean,
    const float* __restrict__ stdv)
{
    __shared__ int hist[1024];          // [0:512) patch A, [512:1024) patch B
    __shared__ float weA[8], weB[8];
    const int t = threadIdx.x;          // 256 threads
    hist[t] = 0; hist[t + 256] = 0; hist[t + 512] = 0; hist[t + 768] = 0;
    __syncthreads();

    const int pA = blockIdx.x * 2;      // two coarse patches, same batch/row
    const int b  = pA >> 8;
    const int icA = (pA >> 4) & 15, jcA = pA & 15;
    const int icB = ((pA + 1) >> 4) & 15, jcB = (pA + 1) & 15;
    const float s0 = stdv[0] * 255.0f, s1 = stdv[1] * 255.0f, s2 = stdv[2] * 255.0f;
    const float m0 = mean[0] * 255.0f, m1 = mean[1] * 255.0f, m2 = mean[2] * 255.0f;
    const float4* base4 = (const float4*)(img + (size_t)b * 786432);

    const u64 pol = l2_evict_last_policy();
    const int r  = t >> 3;
    const int f4 = t & 7;
    const int aA = (icA * 32 + r) * 128 + jcA * 8 + f4;
    const int aB = (icB * 32 + r) * 128 + jcB * 8 + f4;
    // 6 independent loads issued back-to-back (MLP=6)
    float4 vA0 = ldg_evict_last(base4 + aA, pol);
    float4 vA1 = ldg_evict_last(base4 + 65536 + aA, pol);
    float4 vA2 = ldg_evict_last(base4 + 131072 + aA, pol);
    float4 vB0 = ldg_evict_last(base4 + aB, pol);
    float4 vB1 = ldg_evict_last(base4 + 65536 + aB, pol);
    float4 vB2 = ldg_evict_last(base4 + 131072 + aB, pol);

    #pragma unroll
    for (int i = 0; i < 4; i++) {
        float u0 = fminf(fmaxf(fmaf((&vA0.x)[i], s0, m0), 0.0f), 255.0f);
        float u1 = fminf(fmaxf(fmaf((&vA1.x)[i], s1, m1), 0.0f), 255.0f);
        float u2 = fminf(fmaxf(fmaf((&vA2.x)[i], s2, m2), 0.0f), 255.0f);
        float gray = fmaf(u0, 0.2989f, fmaf(u1, 0.587f, u2 * 0.114f));
        atomicAdd(&hist[(int)(gray * 2.0f)], 1);

        float w0 = fminf(fmaxf(fmaf((&vB0.x)[i], s0, m0), 0.0f), 255.0f);
        float w1 = fminf(fmaxf(fmaf((&vB1.x)[i], s1, m1), 0.0f), 255.0f);
        float w2 = fminf(fmaxf(fmaf((&vB2.x)[i], s2, m2), 0.0f), 255.0f);
        float grayB = fmaf(w0, 0.2989f, fmaf(w1, 0.587f, w2 * 0.114f));
        atomicAdd(&hist[512 + (int)(grayB * 2.0f)], 1);
    }
    __syncthreads();

    float eA = 0.0f, eB = 0.0f;
    #pragma unroll
    for (int i = 0; i < 2; i++) {
        int cA = hist[t + i * 256];
        if (cA) {
            float pr = (float)cA * (1.0f / 1024.0f);
            eA -= pr * __log2f(pr + 1e-10f);
        }
        int cB = hist[512 + t + i * 256];
        if (cB) {
            float pr = (float)cB * (1.0f / 1024.0f);
            eB -= pr * __log2f(pr + 1e-10f);
        }
    }
    #pragma unroll
    for (int d = 16; d > 0; d >>= 1) {
        eA += __shfl_down_sync(0xffffffffu, eA, d);
        eB += __shfl_down_sync(0xffffffffu, eB, d);
    }
    int lane = t & 31, wid = t >> 5;
    if (lane == 0) { weA[wid] = eA; weB[wid] = eB; }
    __syncthreads();
    if (t == 0) {
        float sA = 0.0f, sB = 0.0f;
        #pragma unroll
        for (int i = 0; i < 8; i++) { sA += weA[i]; sB += weB[i]; }
        d_m32[pA]     = (sA < 7.2f) ? 1 : 0;
        d_m32[pA + 1] = (sB < 7.2f) ? 1 : 0;
    }
}

// ---------------- block-wide exclusive scan (blockDim = 1024) --------------
__device__ __forceinline__ int block_excl_scan(int v, int& tot)
{
    __shared__ int ws[32];
    __shared__ int stot;
    const int lane = threadIdx.x & 31, wid = threadIdx.x >> 5;
    int x = v;
    #pragma unroll
    for (int d = 1; d < 32; d <<= 1) {
        int y = __shfl_up_sync(0xffffffffu, x, d);
        if (lane >= d) x += y;
    }
    if (lane == 31) ws[wid] = x;
    __syncthreads();
    if (wid == 0) {
        int w = ws[lane];
        int xx = w;
        #pragma unroll
        for (int d = 1; d < 32; d <<= 1) {
            int y = __shfl_up_sync(0xffffffffu, xx, d);
            if (lane >= d) xx += y;
        }
        ws[lane] = xx - w;              // exclusive warp-prefix
        if (lane == 31) stot = xx;
    }
    __syncthreads();
    tot = stot;
    int rr = ws[wid] + x - v;
    __syncthreads();
    return rr;
}

// ---------------- Kernel 2: coarse prefix sum + scalar outputs -------------
// PDL secondary: wait for entropy grid before reading d_m32.
__global__ void __launch_bounds__(1024) scan_kernel(float* __restrict__ out)
{
    const int t = threadIdx.x;          // 1024 threads, 1 block
    __shared__ int sh_n32[32];
    __shared__ int sh_cu[33];

    cudaGridDependencySynchronize();    // entropy's d_m32 writes visible after

    // coarse scan: 8 elems/thread
    int cv[8]; int csum = 0;
    #pragma unroll
    for (int i = 0; i < 8; i++) { cv[i] = d_m32[t * 8 + i]; csum += cv[i]; }
    int tot32;
    int cex = block_excl_scan(csum, tot32);
    {
        int e = cex;
        #pragma unroll
        for (int i = 0; i < 8; i++) { d_idx32[t * 8 + i] = e; e += cv[i]; }
    }
    __syncthreads();

    const int N32 = tot32;
    const int N16 = NFINE - 4 * N32;

    if (t < 32) {
        int start = d_idx32[t * 256];
        int end   = (t == 31) ? N32 : d_idx32[(t + 1) * 256];
        sh_n32[t] = end - start;
    }
    __syncthreads();
    if (t == 0) {
        int acc = 0; sh_cu[0] = 0;
        for (int b = 0; b < 32; b++) { acc += 1025 - 3 * sh_n32[b]; sh_cu[b + 1] = acc; }
    }
    __syncthreads();

    const int sumseq   = sh_cu[32];           // = 32 + N16 + N32
    const int OFF1     = N16 * 768;
    const int OFF2     = OFF1 + N32 * 3072;
    const int OFF_f16  = OFF2 + N32 * 768;
    const int OFF_f32  = OFF_f16 + NFINE;
    const int OFF_mask = OFF_f32 + NCOARSE;
    const int OFF_seq  = OFF_mask + sumseq;
    const int OFF_cu   = OFF_seq + 32;
    const int OFF_max  = OFF_cu + 33;
    const int OFF_frac = OFF_max + 1;

    if (t < 32) {
        d_n32b[t] = sh_n32[t];
        d_cu[t]   = sh_cu[t];
        out[OFF_seq + t] = (float)(1025 - 3 * sh_n32[t]);
        out[OFF_cu + t]  = (float)sh_cu[t];
    }
    if (t == 0) {
        d_idx32[NCOARSE] = N32;               // sentinel for row-end lookups
        d_cu[32] = sh_cu[32];
        d_off[0] = N16 * 192;                 // full32 start, float4 units
        d_off[1] = N16 * 192 + N32 * 768;     // sel32 start, float4 units
        d_off[2] = OFF_f16;
        d_off[3] = OFF_f32;
        d_off[4] = OFF_mask;
        d_off[5] = sumseq;
        out[OFF_cu + 32] = (float)sh_cu[32];
        int mx = 0;
        for (int b = 0; b < 32; b++) mx = max(mx, 1025 - 3 * sh_n32[b]);
        out[OFF_max]  = (float)mx;
        out[OFF_frac] = (float)sumseq / 32768.0f;
    }
}

// ---------------- Kernel 3: gathers (reverse order) + dense fills ----------
// PDL secondary: prologue runs during scan's tail. 384 threads, 8 patches/
// block, grid 1024, reverse p order.
__global__ void __launch_bounds__(384) gather_kernel(
    const float* __restrict__ img, float* __restrict__ out)
{
    const int B  = blockIdx.x;         // 1024 blocks
    const int t  = threadIdx.x;        // 384 threads
    const int p0 = (1023 - B) * 8;     // reverse order; 8 patches, same row
    const int b  = p0 >> 8;            // 32 blocks per batch
    const float4* base4 = (const float4*)(img + (size_t)b * 786432);
    float4* out4 = (float4*)out;

    const int h  = t >= 192;           // half: patches 4h..4h+3
    const int tl = t - h * 192;        // local thread 0..191
    const int c  = tl >> 6;            // channel 0..2
    const int w0 = tl & 63;
    const int r  = w0 >> 2, s4 = w0 & 3;

    cudaGridDependencySynchronize();   // scan's d_idx32/d_off/d_cu visible after

    const int off0 = d_off[0];
    const int off1 = d_off[1];

    // stage masks + coarse prefixes; derive fine slots analytically
    __shared__ int sm[8], sslot[8], srow[2];   // srow = {idx32[prs], idx32[prs+16]}
    if (t < 8) { sm[t] = d_m32[p0 + t]; sslot[t] = d_idx32[p0 + t]; }
    if (t == 16) srow[0] = d_idx32[p0 & ~15];
    if (t == 17) srow[1] = d_idx32[(p0 & ~15) + 16];
    __syncthreads();

    const int prs    = p0 & ~15;
    const int Urs    = prs - srow[0];               // unkept coarse before row
    const int Urowt  = (prs + 16 - srow[1]) - Urs;  // unkept in whole row

    #pragma unroll
    for (int kq = 0; kq < 4; kq++) {
        const int kp = h * 4 + kq;
        const int p  = p0 + kp;
        const int ic = (p >> 4) & 15;
        const int jc = p & 15;
        float4 v[4];
        #pragma unroll
        for (int k = 0; k < 4; k++) {
            int di = k >> 1, dj = k & 1;
            int y  = ic * 32 + di * 16 + r;
            int xs = jc * 8 + dj * 4 + s4;
            v[k] = base4[c * 65536 + y * 128 + xs];
        }
        if (!sm[kp]) {
            const int u    = 1;                     // this patch unkept
            const int Urow = (p - sslot[kp]) - Urs; // unkept before p in row
            int dst16[4];
            dst16[0] = 4 * Urs + 2 * Urow;              // (di=0,dj=0)
            dst16[1] = dst16[0] + u;                    // (0,1)
            dst16[2] = 4 * Urs + 2 * Urowt + 2 * Urow;  // (1,0)
            dst16[3] = dst16[2] + u;                    // (1,1)
            #pragma unroll
            for (int k = 0; k < 4; k++)
                __stcs(&out4[(size_t)dst16[k] * 192 + c * 64 + w0], v[k]);
        } else {
            const size_t o1 = (size_t)off0 + (size_t)sslot[kp] * 768;
            #pragma unroll
            for (int k = 0; k < 4; k++)
                __stcs(&out4[o1 + k * 192 + c * 64 + w0], v[k]);
            // sel32: 2x2-mean downsample (source lines L1-hot from v[] loads)
            {
                int y0 = ic * 32 + 2 * r;
                int xb = jc * 8 + 2 * s4;
                float4 a0 = base4[c * 65536 + y0 * 128 + xb];
                float4 a1 = base4[c * 65536 + y0 * 128 + xb + 1];
                float4 b0 = base4[c * 65536 + (y0 + 1) * 128 + xb];
                float4 b1 = base4[c * 65536 + (y0 + 1) * 128 + xb + 1];
                float4 o;
                o.x = 0.25f * (a0.x + a0.y + b0.x + b0.y);
                o.y = 0.25f * (a0.z + a0.w + b0.z + b0.w);
                o.z = 0.25f * (a1.x + a1.y + b1.x + b1.y);
                o.w = 0.25f * (a1.z + a1.w + b1.z + b1.w);
                __stcs(&out4[(size_t)off1 + (size_t)sslot[kp] * 192 + tl], o);
            }
        }
    }

    // ---- dense fills: flat16 | flat32 | output_mask -----------------------
    {
        const int gi = B * 384 + t;
        const int T  = 40960 + d_off[5];       // 32768 + 8192 + sumseq
        if (gi < T) {
            if (gi < 32768) {
                int q = gi;
                int m = d_m32[(q >> 10) * 256 + (((q >> 5) & 31) >> 1) * 16 + ((q & 31) >> 1)];
                out[d_off[2] + q] = (float)(1 - m);
            } else if (gi < 40960) {
                int p = gi - 32768;
                out[d_off[3] + p] = (float)d_m32[p];
            } else {
                int j = gi - 40960;            // index into output_mask
                int lo = 0, hi = 32;
                while (hi - lo > 1) {
                    int mid = (lo + hi) >> 1;
                    if (j >= d_cu[mid]) lo = mid; else hi = mid;
                }
                int rel  = j - d_cu[lo];
                int n16b = 1024 - 4 * d_n32b[lo];
                float val = (rel == 0) ? -1.0f : (rel - 1 < n16b ? 1.0f : 2.0f);
                out[d_off[4] + j] = val;
            }
        }
    }
}

// ---------------------------------------------------------------------------
extern "C" void kernel_launch(void* const* d_in, const int* in_sizes, int n_in,
                              void* d_out, int out_size)
{
    const float* img  = (const float*)d_in[0];
    const float* mean = (const float*)d_in[1];
    const float* stdv = (const float*)d_in[2];
    float* out = (float*)d_out;

    entropy_kernel<<<NCOARSE / 2, 256>>>(img, mean, stdv);

    // PDL launches: dependent kernels overlap their prologue with the
    // predecessor's tail; cudaGridDependencySynchronize() guards data reads.
    cudaLaunchAttribute attrs[1];
    attrs[0].id = cudaLaunchAttributeProgrammaticStreamSerialization;
    attrs[0].val.programmaticStreamSerializationAllowed = 1;

    {
        cudaLaunchConfig_t cfg = {};
        cfg.gridDim  = dim3(1, 1, 1);
        cfg.blockDim = dim3(1024, 1, 1);
        cfg.attrs    = attrs;
        cfg.numAttrs = 1;
        cudaLaunchKernelEx(&cfg, scan_kernel, out);
    }
    {
        cudaLaunchConfig_t cfg = {};
        cfg.gridDim  = dim3(1024, 1, 1);
        cfg.blockDim = dim3(384, 1, 1);
        cfg.attrs    = attrs;
        cfg.numAttrs = 1;
        cudaLaunchKernelEx(&cfg, gather_kernel, img, out);
    }
}